// round 16
// baseline (speedup 1.0000x reference)
#include <cuda_runtime.h>
#include <cstdint>

#define B_       2
#define S_       2048
#define DM       1024
#define H_       16
#define HD       64
#define BH_      32
#define MTOT     4096
#define L2E      1.4426950408889634f
#define SCALE_   0.125f
#define KPH      40                  // dense fp16 smem row pad (halves) -> 80B pitch
#define KPQ2     72                  // flash q/k/v fp16 pad (halves) -> 144B pitch

// ---------------- scratch (device globals) ----------------
__device__ __align__(128) uint16_t g_xh[MTOT * DM];            // x fp16
__device__ __align__(128) uint16_t g_qh[MTOT * DM];            // q fp16
__device__ __align__(128) uint16_t g_kh[MTOT * DM];            // k fp16
__device__ __align__(128) uint16_t g_oh[MTOT * DM];            // attn out fp16 (flat)
__device__ __align__(128) uint16_t g_wt[4][DM * DM];           // W^T fp16 [n][k]; [1],[2] contiguous
__device__ __align__(128) uint16_t g_vt[BH_ * HD * S_];        // V^T fp16 per head [bh][e][t]
__device__ __align__(128) uint32_t g_mp[B_ * S_ * (S_ / 32)];  // packed mask bits, 1MB

extern __shared__ char smraw[];

// ---------------- helpers ----------------
__device__ __forceinline__ uint32_t smem_u32(const void* p) {
    uint32_t r;
    asm("{ .reg .u64 t; cvta.to.shared.u64 t, %1; cvt.u32.u64 %0, t; }" : "=r"(r) : "l"(p));
    return r;
}
__device__ __forceinline__ uint16_t f2h(float x) {
    uint16_t h; asm("cvt.rn.f16.f32 %0, %1;" : "=h"(h) : "f"(x)); return h;
}
__device__ __forceinline__ uint32_t cvth2(float lo, float hi) {  // pack {lo,hi} -> f16x2
    uint32_t r; asm("cvt.rn.f16x2.f32 %0, %1, %2;" : "=r"(r) : "f"(hi), "f"(lo)); return r;
}
__device__ __forceinline__ float ex2a(float x) {      // MUFU exp2
    float r; asm("ex2.approx.ftz.f32 %0, %1;" : "=f"(r) : "f"(x)); return r;
}
__device__ __forceinline__ void cp16(uint32_t d, const void* s) {   // .ca (R15 showed .cg regresses)
    asm volatile("cp.async.ca.shared.global [%0], [%1], 16;" :: "r"(d), "l"(s));
}
#define CPC()  asm volatile("cp.async.commit_group;")
#define CPW2() asm volatile("cp.async.wait_group 2;")
#define CPW1() asm volatile("cp.async.wait_group 1;")
#define CPW0() asm volatile("cp.async.wait_group 0;")

#define LDSM4(r, addr) \
    asm volatile("ldmatrix.sync.aligned.m8n8.x4.shared.b16 {%0,%1,%2,%3}, [%4];" \
                 : "=r"((r)[0]), "=r"((r)[1]), "=r"((r)[2]), "=r"((r)[3]) : "r"(addr))

__device__ __forceinline__ void mma_h(float* d, const uint32_t* a, const uint32_t* b) {
    asm volatile("mma.sync.aligned.m16n8k16.row.col.f32.f16.f16.f32 "
                 "{%0,%1,%2,%3},{%4,%5,%6,%7},{%8,%9},{%0,%1,%2,%3};"
                 : "+f"(d[0]), "+f"(d[1]), "+f"(d[2]), "+f"(d[3])
                 : "r"(a[0]), "r"(a[1]), "r"(a[2]), "r"(a[3]), "r"(b[0]), "r"(b[1]));
}

// ---------------- dense fp16 mainloop: 4 warps x (64m x 64n), k32 iters, 3-stage ------
// A-fragments loaded up-front per k16 (af[4][4] reused across all j); B streamed one LDSM4
// at a time to minimize live registers -> fits 3 CTAs/SM (170 regs).
#define DTILEH (128 * KPH * 2)         // 10240 B per 128x32 fp16 tile
#define DSTG   (2 * DTILEH)            // 20480
#define DSMEM  (3 * DSTG)              // 61440
__device__ __forceinline__ void dense_mainloop(const uint16_t* Ag, const uint16_t* Bg,
                                               int tid, int lane, int wm, int wn,
                                               float (*acc)[8][4]) {
    const uint32_t sb = smem_u32(smraw);
    auto stg = [&](int s, int k0) {
        uint32_t off = sb + (uint32_t)s * DSTG;
#pragma unroll
        for (int p = 0; p < 4; p++) {
            int id = tid + p * 128;
            int r = id >> 2, c = (id & 3) * 8;       // 8 halves = 16B
            cp16(off + (uint32_t)(r * KPH + c) * 2u, Ag + (size_t)r * DM + k0 + c);
            cp16(off + DTILEH + (uint32_t)(r * KPH + c) * 2u, Bg + (size_t)r * DM + k0 + c);
        }
    };
    stg(0, 0);  CPC();
    stg(1, 32); CPC();

    // ldsm lane bases (bytes; pitch 80B). A: row sel bit3, col sel bit4. B: row sel bit4, col sel bit3.
    const uint32_t la = (uint32_t)((wm * 64 + ((lane >> 3) & 1) * 8 + (lane & 7)) * 80
                                   + ((lane >> 4) & 1) * 16);
    const uint32_t lb = (uint32_t)(DTILEH
                                   + (wn * 64 + ((lane >> 4) & 1) * 8 + (lane & 7)) * 80
                                   + ((lane >> 3) & 1) * 16);
    const int NT = DM / 32;   // 32
    for (int i = 0; i < NT; i++) {
        int s = i % 3;
        if (i >= NT - 2) { CPW0(); } else { CPW1(); }
        __syncthreads();
        const uint32_t abase = sb + (uint32_t)s * DSTG + la;
        const uint32_t bbase = sb + (uint32_t)s * DSTG + lb;
#pragma unroll
        for (int kh = 0; kh < 2; kh++) {            // 2 x k16 per k32 iter
            uint32_t af[4][4];
#pragma unroll
            for (int ii = 0; ii < 4; ii++) LDSM4(af[ii], abase + kh * 32 + ii * (16 * 80));
#pragma unroll
            for (int jj = 0; jj < 4; jj++) {
                uint32_t bf[4];
                LDSM4(bf, bbase + kh * 32 + jj * (16 * 80));
#pragma unroll
                for (int ii = 0; ii < 4; ii++) {
                    mma_h(acc[ii][jj * 2 + 0], af[ii], &bf[0]);
                    mma_h(acc[ii][jj * 2 + 1], af[ii], &bf[2]);
                }
            }
        }
        if (i + 2 < NT) { stg((i + 2) % 3, (i + 2) * 32); CPC(); }
    }
}

// MODE 0: fp32 C (final).  MODE 2: fp16 Ch (q / k inputs to attention).
template<int MODE>
__global__ __launch_bounds__(128, 3)
void gemm_h(const uint16_t* __restrict__ A, const uint16_t* __restrict__ Bt,
            const float* __restrict__ bias, float* __restrict__ C,
            uint16_t* __restrict__ Ch) {
    const int tid = threadIdx.x, lane = tid & 31, wid = tid >> 5;
    const int wm = wid & 1, wn = wid >> 1;
    const int m0 = blockIdx.y * 128, n0 = blockIdx.x * 128;
    float acc[4][8][4];
#pragma unroll
    for (int i = 0; i < 4; i++)
#pragma unroll
        for (int j = 0; j < 8; j++)
#pragma unroll
            for (int e = 0; e < 4; e++) acc[i][j][e] = 0.0f;
    dense_mainloop(A + (size_t)m0 * DM, Bt + (size_t)n0 * DM, tid, lane, wm, wn, acc);
#pragma unroll
    for (int i = 0; i < 4; i++)
#pragma unroll
        for (int j = 0; j < 8; j++) {
            int m = m0 + wm * 64 + i * 16 + (lane >> 2);
            int n = n0 + wn * 64 + j * 8 + (lane & 3) * 2;
            float bz0 = bias[n], bz1 = bias[n + 1];
            float v00 = fmaxf(acc[i][j][0] + bz0, 0.0f), v01 = fmaxf(acc[i][j][1] + bz1, 0.0f);
            float v10 = fmaxf(acc[i][j][2] + bz0, 0.0f), v11 = fmaxf(acc[i][j][3] + bz1, 0.0f);
            if (MODE == 0) {
                *(float2*)&C[(size_t)m * DM + n]       = make_float2(v00, v01);
                *(float2*)&C[(size_t)(m + 8) * DM + n] = make_float2(v10, v11);
            } else {
                ((uint32_t*)Ch)[((size_t)m * DM + n) >> 1]       = cvth2(v00, v01);
                ((uint32_t*)Ch)[((size_t)(m + 8) * DM + n) >> 1] = cvth2(v10, v11);
            }
        }
}

// merged K+V GEMM: B = [W1^T ; W2^T] (2048 rows), n<1024 -> kh (fp16), n>=1024 -> vt (fp16 per head)
__global__ __launch_bounds__(128, 3)
void gemm_kv(const uint16_t* __restrict__ A, const uint16_t* __restrict__ Bt,
             const float* __restrict__ b1, const float* __restrict__ b2,
             uint16_t* __restrict__ K, uint16_t* __restrict__ VT) {
    const int tid = threadIdx.x, lane = tid & 31, wid = tid >> 5;
    const int wm = wid & 1, wn = wid >> 1;
    const int m0 = blockIdx.y * 128, n0 = blockIdx.x * 128;   // n0 in [0,2048)
    float acc[4][8][4];
#pragma unroll
    for (int i = 0; i < 4; i++)
#pragma unroll
        for (int j = 0; j < 8; j++)
#pragma unroll
            for (int e = 0; e < 4; e++) acc[i][j][e] = 0.0f;
    dense_mainloop(A + (size_t)m0 * DM, Bt + (size_t)n0 * DM, tid, lane, wm, wn, acc);
    const bool isK = (n0 < DM);
    const float* bias = isK ? b1 : b2;
    const int nb = isK ? n0 : (n0 - DM);
#pragma unroll
    for (int i = 0; i < 4; i++)
#pragma unroll
        for (int j = 0; j < 8; j++) {
            int m = m0 + wm * 64 + i * 16 + (lane >> 2);
            int n = nb + wn * 64 + j * 8 + (lane & 3) * 2;
            float bz0 = bias[n], bz1 = bias[n + 1];
            float v00 = fmaxf(acc[i][j][0] + bz0, 0.0f), v01 = fmaxf(acc[i][j][1] + bz1, 0.0f);
            float v10 = fmaxf(acc[i][j][2] + bz0, 0.0f), v11 = fmaxf(acc[i][j][3] + bz1, 0.0f);
            if (isK) {
                ((uint32_t*)K)[((size_t)m * DM + n) >> 1]       = cvth2(v00, v01);
                ((uint32_t*)K)[((size_t)(m + 8) * DM + n) >> 1] = cvth2(v10, v11);
            } else {
                int bb = m >> 11, t = m & 2047, hh = n >> 6, e = n & 63;
                size_t base = ((size_t)(bb * 16 + hh) * 64 + e) * S_;
                VT[base + t]          = f2h(v00);
                VT[base + S_ + t]     = f2h(v01);
                VT[base + t + 8]      = f2h(v10);
                VT[base + S_ + t + 8] = f2h(v11);
            }
        }
}

// ---------------- fused flash attention: 128-row s-tile, 4 warps x (32m x 64t), 3-stage ----------
// (exactly the R14 configuration — measured best)
#define QSZ    (128 * KPQ2 * 2)        // 18432
#define KST    (64 * KPQ2 * 2)         // 9216
#define KOFF   QSZ                     // 18432
#define VOFF   (KOFF + 3 * KST)        // 46080
#define FSMEM  (VOFF + 3 * KST)        // 73728
#define TT     64
#define ITERS  (S_ / TT)   // 32
__global__ __launch_bounds__(128, 2)
void flash_attn(const uint16_t* __restrict__ q, const uint16_t* __restrict__ k,
                const uint16_t* __restrict__ vtb, const uint32_t* __restrict__ mp,
                uint16_t* __restrict__ O) {
    char* sm = smraw;
    const int tid = threadIdx.x, lane = tid & 31, wm = tid >> 5;   // 4 warps, 32 m-rows each
    const int bh = blockIdx.y, b = bh >> 4, h = bh & 15;
    const int s0 = blockIdx.x * 128;
    const uint32_t sb = smem_u32(sm);

    const uint16_t* qg = q + ((size_t)b * S_ + s0) * DM + h * HD;
    const uint16_t* kg = k + (size_t)b * S_ * DM + h * HD;
    const uint16_t* vg = vtb + (size_t)bh * HD * S_;

#pragma unroll
    for (int p = 0; p < 8; p++) {        // q: 128 rows x 8 chunks
        int id = tid + p * 128, r = id >> 3, c = (id & 7) * 8;
        cp16(sb + (uint32_t)(r * KPQ2 + c) * 2u, qg + (size_t)r * DM + c);
    }
    CPC();
    auto stage_k = [&](int s, int t0) {
        const uint16_t* src = kg + (size_t)t0 * DM;
        uint32_t koff = KOFF + (uint32_t)s * KST;
#pragma unroll
        for (int p = 0; p < 4; p++) {
            int id = tid + p * 128, r = id >> 3, c = (id & 7) * 8;
            cp16(sb + koff + (uint32_t)(r * KPQ2 + c) * 2u, src + (size_t)r * DM + c);
        }
    };
    auto stage_v = [&](int s, int t0) {
        uint32_t voff = VOFF + (uint32_t)s * KST;
#pragma unroll
        for (int p = 0; p < 4; p++) {
            int id = tid + p * 128, e = id >> 3, c = (id & 7) * 8;
            cp16(sb + voff + (uint32_t)(e * KPQ2 + c) * 2u, vg + (size_t)e * S_ + t0 + c);
        }
    };
    stage_k(0, 0);  stage_v(0, 0);  CPC();
    stage_k(1, TT); stage_v(1, TT); CPC();

    const int bpl = (lane & 3) * 2;

    CPW2();             // q group complete
    __syncthreads();
    // hoist Q A-fragments: 2 m16 tiles x 4 k16 chunks (ldsm; row sel bit3, col sel bit4)
    uint32_t Qf[2][4][4];
#pragma unroll
    for (int im = 0; im < 2; im++) {
        uint32_t qb = sb + (uint32_t)((wm * 32 + im * 16 + ((lane >> 3) & 1) * 8 + (lane & 7)) * 144
                                      + ((lane >> 4) & 1) * 16);
#pragma unroll
        for (int kc = 0; kc < 4; kc++) LDSM4(Qf[im][kc], qb + kc * 32);
    }

    float acc2[2][8][4];
#pragma unroll
    for (int im = 0; im < 2; im++)
#pragma unroll
        for (int j = 0; j < 8; j++)
#pragma unroll
            for (int e = 0; e < 4; e++) acc2[im][j][e] = 0.0f;
    float rs[2][2] = {{0.f, 0.f}, {0.f, 0.f}};

    const float cf = SCALE_ * L2E;
    const uint32_t* mpr[2];
#pragma unroll
    for (int im = 0; im < 2; im++) {
        int row = s0 + wm * 32 + im * 16 + (lane >> 2);
        mpr[im] = mp + ((size_t)(b * S_ + row) << 6);
    }
    // K/V B-fragment lane base (row sel bit4, col sel bit3); pitch 144B
    const uint32_t lkv = (uint32_t)((((lane >> 4) & 1) * 8 + (lane & 7)) * 144
                                    + ((lane >> 3) & 1) * 16);

    for (int it = 0; it < ITERS; it++) {
        const int s = it % 3;
        if (it >= ITERS - 2) { CPW0(); } else { CPW1(); }
        __syncthreads();
        const uint32_t kbase = sb + KOFF + (uint32_t)s * KST + lkv;
        const uint32_t vbase = sb + VOFF + (uint32_t)s * KST + lkv;

        float acc[2][8][4];
#pragma unroll
        for (int im = 0; im < 2; im++)
#pragma unroll
            for (int j = 0; j < 8; j++)
#pragma unroll
                for (int e = 0; e < 4; e++) acc[im][j][e] = 0.0f;
#pragma unroll
        for (int kc = 0; kc < 4; kc++) {             // 4 x k16 over head dim
            uint32_t kf[4][4];
#pragma unroll
            for (int tg = 0; tg < 4; tg++) LDSM4(kf[tg], kbase + kc * 32 + tg * (16 * 144));
#pragma unroll
            for (int im = 0; im < 2; im++)
#pragma unroll
                for (int j = 0; j < 8; j++)
                    mma_h(acc[im][j], Qf[im][kc], &kf[j >> 1][(j & 1) * 2]);
        }

        uint32_t w[2][2], w8[2][2];
#pragma unroll
        for (int im = 0; im < 2; im++) {
            w[im][0]  = mpr[im][it * 2];       w[im][1]  = mpr[im][it * 2 + 1];
            w8[im][0] = mpr[im][512 + it * 2]; w8[im][1] = mpr[im][512 + it * 2 + 1];
        }
#pragma unroll
        for (int st = 0; st < 4; st++) {
            uint32_t af[2][4];
#pragma unroll
            for (int im = 0; im < 2; im++)
#pragma unroll
                for (int jj = 0; jj < 2; jj++) {
                    const int j = st * 2 + jj;
                    const int bp = (j * 8) & 31;
                    const int wsel = (j >> 2);
                    const uint32_t wl = w[im][wsel], wh = w8[im][wsel];
                    float e00 = ex2a(((wl >> (bp + bpl)) & 1u)     ? acc[im][j][0] * cf : -12000.0f);
                    float e01 = ex2a(((wl >> (bp + bpl + 1)) & 1u) ? acc[im][j][1] * cf : -12000.0f);
                    float e10 = ex2a(((wh >> (bp + bpl)) & 1u)     ? acc[im][j][2] * cf : -12000.0f);
                    float e11 = ex2a(((wh >> (bp + bpl + 1)) & 1u) ? acc[im][j][3] * cf : -12000.0f);
                    rs[im][0] += e00 + e01;
                    rs[im][1] += e10 + e11;
                    af[im][jj * 2 + 0] = cvth2(e00, e01);
                    af[im][jj * 2 + 1] = cvth2(e10, e11);
                }
            uint32_t vf[4][4];
#pragma unroll
            for (int eg = 0; eg < 4; eg++) LDSM4(vf[eg], vbase + st * 32 + eg * (16 * 144));
#pragma unroll
            for (int im = 0; im < 2; im++)
#pragma unroll
                for (int eg = 0; eg < 4; eg++) {
                    mma_h(acc2[im][eg * 2 + 0], af[im], &vf[eg][0]);
                    mma_h(acc2[im][eg * 2 + 1], af[im], &vf[eg][2]);
                }
        }
        if (it + 2 < ITERS) {
            int sp = (it + 2) % 3;
            stage_k(sp, (it + 2) * TT);
            stage_v(sp, (it + 2) * TT);
            CPC();
        }
    }

    // row sums: quad shuffle (lanes in a quad share the same row)
#pragma unroll
    for (int im = 0; im < 2; im++)
#pragma unroll
        for (int r = 0; r < 2; r++) {
            rs[im][r] += __shfl_xor_sync(0xffffffffu, rs[im][r], 1);
            rs[im][r] += __shfl_xor_sync(0xffffffffu, rs[im][r], 2);
        }

    // epilogue: each warp owns its rows fully -> direct write, no smem
#pragma unroll
    for (int im = 0; im < 2; im++) {
        int row = s0 + wm * 32 + im * 16 + (lane >> 2);
        float inv0 = 1.0f / rs[im][0];
        float inv1 = 1.0f / rs[im][1];
#pragma unroll
        for (int je = 0; je < 8; je++) {
            int cl = je * 8 + (lane & 3) * 2;
            ((uint32_t*)O)[(((size_t)bh * S_ + row) * HD + cl) >> 1] =
                cvth2(acc2[im][je][0] * inv0, acc2[im][je][1] * inv0);
            ((uint32_t*)O)[(((size_t)bh * S_ + row + 8) * HD + cl) >> 1] =
                cvth2(acc2[im][je][2] * inv1, acc2[im][je][3] * inv1);
        }
    }
}

// ---------------- small utility kernels ----------------
__global__ __launch_bounds__(256)
void conv_x(const float* __restrict__ X, uint16_t* __restrict__ Xh) {
    size_t i = (size_t)blockIdx.x * 256 + threadIdx.x;
    float2 v = ((const float2*)X)[i];
    ((uint32_t*)Xh)[i] = cvth2(v.x, v.y);
}

__global__ __launch_bounds__(256)
void maskpack(const int* __restrict__ mask, uint32_t* __restrict__ mp) {
    int w = blockIdx.x * 256 + threadIdx.x;
    const int4* src = (const int4*)mask + (size_t)w * 8;
    uint32_t bits = 0;
#pragma unroll
    for (int i = 0; i < 8; i++) {
        int4 v = src[i];
        bits |= (uint32_t)(v.x == 1) << (i * 4 + 0);
        bits |= (uint32_t)(v.y == 1) << (i * 4 + 1);
        bits |= (uint32_t)(v.z == 1) << (i * 4 + 2);
        bits |= (uint32_t)(v.w == 1) << (i * 4 + 3);
    }
    mp[w] = bits;
}

__global__ __launch_bounds__(256)
void transpose_h(const float* __restrict__ Wa, const float* __restrict__ Wb,
                 const float* __restrict__ Wc, const float* __restrict__ Wd,
                 uint16_t* __restrict__ Wt) {
    __shared__ float t[32][33];
    const int z = blockIdx.z;
    const float* W = (z == 0) ? Wa : (z == 1) ? Wb : (z == 2) ? Wc : Wd;
    uint16_t* Wo = Wt + (size_t)z * DM * DM;
    const int tx = threadIdx.x & 31, ty = threadIdx.x >> 5;
    const int bx = blockIdx.x * 32, by = blockIdx.y * 32;
#pragma unroll
    for (int j = 0; j < 32; j += 8) t[ty + j][tx] = W[(size_t)(by + ty + j) * DM + bx + tx];
    __syncthreads();
#pragma unroll
    for (int j = 0; j < 32; j += 8)
        Wo[(size_t)(bx + ty + j) * DM + by + tx] = f2h(t[tx][ty + j]);
}

// ---------------- launch ----------------
extern "C" void kernel_launch(void* const* d_in, const int* in_sizes, int n_in,
                              void* d_out, int out_size) {
    (void)in_sizes; (void)n_in; (void)out_size;
    const float* x    = (const float*)d_in[0];
    const int*   mask = (const int*)d_in[1];
    const float* W0   = (const float*)d_in[2];
    const float* b0   = (const float*)d_in[3];
    const float* W1   = (const float*)d_in[4];
    const float* b1   = (const float*)d_in[5];
    const float* W2   = (const float*)d_in[6];
    const float* b2   = (const float*)d_in[7];
    const float* Wo   = (const float*)d_in[8];
    const float* bo   = (const float*)d_in[9];
    float* out = (float*)d_out;

    uint16_t *xh, *qh, *kh, *oh, *wt, *vt;
    uint32_t *mpd;
    cudaGetSymbolAddress((void**)&xh,  g_xh);
    cudaGetSymbolAddress((void**)&qh,  g_qh);
    cudaGetSymbolAddress((void**)&kh,  g_kh);
    cudaGetSymbolAddress((void**)&oh,  g_oh);
    cudaGetSymbolAddress((void**)&wt,  g_wt);
    cudaGetSymbolAddress((void**)&vt,  g_vt);
    cudaGetSymbolAddress((void**)&mpd, g_mp);
    const size_t WP = (size_t)DM * DM;

    cudaFuncSetAttribute(gemm_h<0>, cudaFuncAttributeMaxDynamicSharedMemorySize, DSMEM);
    cudaFuncSetAttribute(gemm_h<2>, cudaFuncAttributeMaxDynamicSharedMemorySize, DSMEM);
    cudaFuncSetAttribute(gemm_kv,   cudaFuncAttributeMaxDynamicSharedMemorySize, DSMEM);
    cudaFuncSetAttribute(flash_attn, cudaFuncAttributeMaxDynamicSharedMemorySize, FSMEM);

    conv_x<<<MTOT * DM / 512, 256>>>(x, xh);
    maskpack<<<(B_ * S_ * 64) / 256, 256>>>(mask, mpd);
    transpose_h<<<dim3(32, 32, 4), 256>>>(W0, W1, W2, Wo, wt);

    gemm_h<2><<<dim3(8, 32), 128, DSMEM>>>(xh, wt + 0 * WP, b0, nullptr, qh);
    gemm_kv<<<dim3(16, 32), 128, DSMEM>>>(qh, wt + 1 * WP, b1, b2, kh, vt);
    flash_attn<<<dim3(16, 32), 128, FSMEM>>>(qh, kh, vt, mpd, oh);
    gemm_h<0><<<dim3(8, 32), 128, DSMEM>>>(oh, wt + 3 * WP, bo, out, nullptr);
}

// round 17
// speedup vs baseline: 1.0642x; 1.0642x over previous
#include <cuda_runtime.h>
#include <cstdint>

#define B_       2
#define S_       2048
#define DM       1024
#define H_       16
#define HD       64
#define BH_      32
#define MTOT     4096
#define L2E      1.4426950408889634f
#define SCALE_   0.125f
#define KPH      40                  // dense fp16 smem row pad (halves) -> 80B pitch
#define KPQ2     72                  // flash q/k/v fp16 pad (halves) -> 144B pitch

// ---------------- scratch (device globals) ----------------
__device__ __align__(128) uint16_t g_xh[MTOT * DM];            // x fp16
__device__ __align__(128) uint16_t g_qh[MTOT * DM];            // q fp16
__device__ __align__(128) uint16_t g_kh[MTOT * DM];            // k fp16
__device__ __align__(128) uint16_t g_oh[MTOT * DM];            // attn out fp16 (flat)
__device__ __align__(128) uint16_t g_wt[4][DM * DM];           // W^T fp16 [n][k]; [1],[2] contiguous
__device__ __align__(128) uint16_t g_vt[BH_ * HD * S_];        // V^T fp16 per head [bh][e][t]
__device__ __align__(128) uint32_t g_mp[B_ * S_ * (S_ / 32)];  // packed mask bits, 1MB

extern __shared__ char smraw[];

// ---------------- helpers ----------------
__device__ __forceinline__ uint32_t smem_u32(const void* p) {
    uint32_t r;
    asm("{ .reg .u64 t; cvta.to.shared.u64 t, %1; cvt.u32.u64 %0, t; }" : "=r"(r) : "l"(p));
    return r;
}
__device__ __forceinline__ uint16_t f2h(float x) {
    uint16_t h; asm("cvt.rn.f16.f32 %0, %1;" : "=h"(h) : "f"(x)); return h;
}
__device__ __forceinline__ uint32_t cvth2(float lo, float hi) {  // pack {lo,hi} -> f16x2
    uint32_t r; asm("cvt.rn.f16x2.f32 %0, %1, %2;" : "=r"(r) : "f"(hi), "f"(lo)); return r;
}
__device__ __forceinline__ float ex2a(float x) {      // MUFU exp2
    float r; asm("ex2.approx.ftz.f32 %0, %1;" : "=f"(r) : "f"(x)); return r;
}
__device__ __forceinline__ void cp16(uint32_t d, const void* s) {   // .ca (R15: .cg regresses)
    asm volatile("cp.async.ca.shared.global [%0], [%1], 16;" :: "r"(d), "l"(s));
}
#define CPC()  asm volatile("cp.async.commit_group;")
#define CPW2() asm volatile("cp.async.wait_group 2;")
#define CPW1() asm volatile("cp.async.wait_group 1;")
#define CPW0() asm volatile("cp.async.wait_group 0;")

#define LDSM4(r, addr) \
    asm volatile("ldmatrix.sync.aligned.m8n8.x4.shared.b16 {%0,%1,%2,%3}, [%4];" \
                 : "=r"((r)[0]), "=r"((r)[1]), "=r"((r)[2]), "=r"((r)[3]) : "r"(addr))

__device__ __forceinline__ void mma_h(float* d, const uint32_t* a, const uint32_t* b) {
    asm volatile("mma.sync.aligned.m16n8k16.row.col.f32.f16.f16.f32 "
                 "{%0,%1,%2,%3},{%4,%5,%6,%7},{%8,%9},{%0,%1,%2,%3};"
                 : "+f"(d[0]), "+f"(d[1]), "+f"(d[2]), "+f"(d[3])
                 : "r"(a[0]), "r"(a[1]), "r"(a[2]), "r"(a[3]), "r"(b[0]), "r"(b[1]));
}

// ---------------- dense fp16 mainloop: EXACT R14 config (measured best) ------
// 4 warps x (64m x 64n), k32 iters, 3-stage, bf[4][4]+af[4] live (255 regs, 2 CTA/SM)
#define DTILEH (128 * KPH * 2)         // 10240 B per 128x32 fp16 tile
#define DSTG   (2 * DTILEH)            // 20480
#define DSMEM  (3 * DSTG)              // 61440
__device__ __forceinline__ void dense_mainloop(const uint16_t* Ag, const uint16_t* Bg,
                                               int tid, int lane, int wm, int wn,
                                               float (*acc)[8][4]) {
    const uint32_t sb = smem_u32(smraw);
    auto stg = [&](int s, int k0) {
        uint32_t off = sb + (uint32_t)s * DSTG;
#pragma unroll
        for (int p = 0; p < 4; p++) {
            int id = tid + p * 128;
            int r = id >> 2, c = (id & 3) * 8;       // 8 halves = 16B
            cp16(off + (uint32_t)(r * KPH + c) * 2u, Ag + (size_t)r * DM + k0 + c);
            cp16(off + DTILEH + (uint32_t)(r * KPH + c) * 2u, Bg + (size_t)r * DM + k0 + c);
        }
    };
    stg(0, 0);  CPC();
    stg(1, 32); CPC();

    // ldsm lane bases (bytes; pitch 80B). A: row sel bit3, col sel bit4. B: row sel bit4, col sel bit3.
    const uint32_t la = (uint32_t)((wm * 64 + ((lane >> 3) & 1) * 8 + (lane & 7)) * 80
                                   + ((lane >> 4) & 1) * 16);
    const uint32_t lb = (uint32_t)(DTILEH
                                   + (wn * 64 + ((lane >> 4) & 1) * 8 + (lane & 7)) * 80
                                   + ((lane >> 3) & 1) * 16);
    const int NT = DM / 32;   // 32
    for (int i = 0; i < NT; i++) {
        int s = i % 3;
        if (i >= NT - 2) { CPW0(); } else { CPW1(); }
        __syncthreads();
        const uint32_t abase = sb + (uint32_t)s * DSTG + la;
        const uint32_t bbase = sb + (uint32_t)s * DSTG + lb;
#pragma unroll
        for (int kh = 0; kh < 2; kh++) {            // 2 x k16 per k32 iter
            uint32_t bf[4][4];
#pragma unroll
            for (int jj = 0; jj < 4; jj++) LDSM4(bf[jj], bbase + kh * 32 + jj * (16 * 80));
#pragma unroll
            for (int ii = 0; ii < 4; ii++) {
                uint32_t af[4];
                LDSM4(af, abase + kh * 32 + ii * (16 * 80));
#pragma unroll
                for (int j = 0; j < 8; j++)
                    mma_h(acc[ii][j], af, &bf[j >> 1][(j & 1) * 2]);
            }
        }
        if (i + 2 < NT) { stg((i + 2) % 3, (i + 2) * 32); CPC(); }
    }
}

// MODE 0: fp32 C (final).  MODE 2: fp16 Ch (q / k inputs to attention).
template<int MODE>
__global__ __launch_bounds__(128, 2)
void gemm_h(const uint16_t* __restrict__ A, const uint16_t* __restrict__ Bt,
            const float* __restrict__ bias, float* __restrict__ C,
            uint16_t* __restrict__ Ch) {
    const int tid = threadIdx.x, lane = tid & 31, wid = tid >> 5;
    const int wm = wid & 1, wn = wid >> 1;
    const int m0 = blockIdx.y * 128, n0 = blockIdx.x * 128;
    float acc[4][8][4];
#pragma unroll
    for (int i = 0; i < 4; i++)
#pragma unroll
        for (int j = 0; j < 8; j++)
#pragma unroll
            for (int e = 0; e < 4; e++) acc[i][j][e] = 0.0f;
    dense_mainloop(A + (size_t)m0 * DM, Bt + (size_t)n0 * DM, tid, lane, wm, wn, acc);
#pragma unroll
    for (int i = 0; i < 4; i++)
#pragma unroll
        for (int j = 0; j < 8; j++) {
            int m = m0 + wm * 64 + i * 16 + (lane >> 2);
            int n = n0 + wn * 64 + j * 8 + (lane & 3) * 2;
            float bz0 = bias[n], bz1 = bias[n + 1];
            float v00 = fmaxf(acc[i][j][0] + bz0, 0.0f), v01 = fmaxf(acc[i][j][1] + bz1, 0.0f);
            float v10 = fmaxf(acc[i][j][2] + bz0, 0.0f), v11 = fmaxf(acc[i][j][3] + bz1, 0.0f);
            if (MODE == 0) {
                *(float2*)&C[(size_t)m * DM + n]       = make_float2(v00, v01);
                *(float2*)&C[(size_t)(m + 8) * DM + n] = make_float2(v10, v11);
            } else {
                ((uint32_t*)Ch)[((size_t)m * DM + n) >> 1]       = cvth2(v00, v01);
                ((uint32_t*)Ch)[((size_t)(m + 8) * DM + n) >> 1] = cvth2(v10, v11);
            }
        }
}

// merged K+V GEMM: B = [W1^T ; W2^T] (2048 rows), n<1024 -> kh (fp16), n>=1024 -> vt (fp16 per head)
__global__ __launch_bounds__(128, 2)
void gemm_kv(const uint16_t* __restrict__ A, const uint16_t* __restrict__ Bt,
             const float* __restrict__ b1, const float* __restrict__ b2,
             uint16_t* __restrict__ K, uint16_t* __restrict__ VT) {
    const int tid = threadIdx.x, lane = tid & 31, wid = tid >> 5;
    const int wm = wid & 1, wn = wid >> 1;
    const int m0 = blockIdx.y * 128, n0 = blockIdx.x * 128;   // n0 in [0,2048)
    float acc[4][8][4];
#pragma unroll
    for (int i = 0; i < 4; i++)
#pragma unroll
        for (int j = 0; j < 8; j++)
#pragma unroll
            for (int e = 0; e < 4; e++) acc[i][j][e] = 0.0f;
    dense_mainloop(A + (size_t)m0 * DM, Bt + (size_t)n0 * DM, tid, lane, wm, wn, acc);
    const bool isK = (n0 < DM);
    const float* bias = isK ? b1 : b2;
    const int nb = isK ? n0 : (n0 - DM);
#pragma unroll
    for (int i = 0; i < 4; i++)
#pragma unroll
        for (int j = 0; j < 8; j++) {
            int m = m0 + wm * 64 + i * 16 + (lane >> 2);
            int n = nb + wn * 64 + j * 8 + (lane & 3) * 2;
            float bz0 = bias[n], bz1 = bias[n + 1];
            float v00 = fmaxf(acc[i][j][0] + bz0, 0.0f), v01 = fmaxf(acc[i][j][1] + bz1, 0.0f);
            float v10 = fmaxf(acc[i][j][2] + bz0, 0.0f), v11 = fmaxf(acc[i][j][3] + bz1, 0.0f);
            if (isK) {
                ((uint32_t*)K)[((size_t)m * DM + n) >> 1]       = cvth2(v00, v01);
                ((uint32_t*)K)[((size_t)(m + 8) * DM + n) >> 1] = cvth2(v10, v11);
            } else {
                int bb = m >> 11, t = m & 2047, hh = n >> 6, e = n & 63;
                size_t base = ((size_t)(bb * 16 + hh) * 64 + e) * S_;
                VT[base + t]          = f2h(v00);
                VT[base + S_ + t]     = f2h(v01);
                VT[base + t + 8]      = f2h(v10);
                VT[base + S_ + t + 8] = f2h(v11);
            }
        }
}

// ---------------- fused flash attention: EXACT R14 config (measured best) ----------
#define QSZ    (128 * KPQ2 * 2)        // 18432
#define KST    (64 * KPQ2 * 2)         // 9216
#define KOFF   QSZ                     // 18432
#define VOFF   (KOFF + 3 * KST)        // 46080
#define FSMEM  (VOFF + 3 * KST)        // 73728
#define TT     64
#define ITERS  (S_ / TT)   // 32
__global__ __launch_bounds__(128, 2)
void flash_attn(const uint16_t* __restrict__ q, const uint16_t* __restrict__ k,
                const uint16_t* __restrict__ vtb, const uint32_t* __restrict__ mp,
                uint16_t* __restrict__ O) {
    char* sm = smraw;
    const int tid = threadIdx.x, lane = tid & 31, wm = tid >> 5;   // 4 warps, 32 m-rows each
    const int bh = blockIdx.y, b = bh >> 4, h = bh & 15;
    const int s0 = blockIdx.x * 128;
    const uint32_t sb = smem_u32(sm);

    const uint16_t* qg = q + ((size_t)b * S_ + s0) * DM + h * HD;
    const uint16_t* kg = k + (size_t)b * S_ * DM + h * HD;
    const uint16_t* vg = vtb + (size_t)bh * HD * S_;

#pragma unroll
    for (int p = 0; p < 8; p++) {        // q: 128 rows x 8 chunks
        int id = tid + p * 128, r = id >> 3, c = (id & 7) * 8;
        cp16(sb + (uint32_t)(r * KPQ2 + c) * 2u, qg + (size_t)r * DM + c);
    }
    CPC();
    auto stage_k = [&](int s, int t0) {
        const uint16_t* src = kg + (size_t)t0 * DM;
        uint32_t koff = KOFF + (uint32_t)s * KST;
#pragma unroll
        for (int p = 0; p < 4; p++) {
            int id = tid + p * 128, r = id >> 3, c = (id & 7) * 8;
            cp16(sb + koff + (uint32_t)(r * KPQ2 + c) * 2u, src + (size_t)r * DM + c);
        }
    };
    auto stage_v = [&](int s, int t0) {
        uint32_t voff = VOFF + (uint32_t)s * KST;
#pragma unroll
        for (int p = 0; p < 4; p++) {
            int id = tid + p * 128, e = id >> 3, c = (id & 7) * 8;
            cp16(sb + voff + (uint32_t)(e * KPQ2 + c) * 2u, vg + (size_t)e * S_ + t0 + c);
        }
    };
    stage_k(0, 0);  stage_v(0, 0);  CPC();
    stage_k(1, TT); stage_v(1, TT); CPC();

    const int bpl = (lane & 3) * 2;

    CPW2();             // q group complete
    __syncthreads();
    // hoist Q A-fragments: 2 m16 tiles x 4 k16 chunks (ldsm; row sel bit3, col sel bit4)
    uint32_t Qf[2][4][4];
#pragma unroll
    for (int im = 0; im < 2; im++) {
        uint32_t qb = sb + (uint32_t)((wm * 32 + im * 16 + ((lane >> 3) & 1) * 8 + (lane & 7)) * 144
                                      + ((lane >> 4) & 1) * 16);
#pragma unroll
        for (int kc = 0; kc < 4; kc++) LDSM4(Qf[im][kc], qb + kc * 32);
    }

    float acc2[2][8][4];
#pragma unroll
    for (int im = 0; im < 2; im++)
#pragma unroll
        for (int j = 0; j < 8; j++)
#pragma unroll
            for (int e = 0; e < 4; e++) acc2[im][j][e] = 0.0f;
    float rs[2][2] = {{0.f, 0.f}, {0.f, 0.f}};

    const float cf = SCALE_ * L2E;
    const uint32_t* mpr[2];
#pragma unroll
    for (int im = 0; im < 2; im++) {
        int row = s0 + wm * 32 + im * 16 + (lane >> 2);
        mpr[im] = mp + ((size_t)(b * S_ + row) << 6);
    }
    // K/V B-fragment lane base (row sel bit4, col sel bit3); pitch 144B
    const uint32_t lkv = (uint32_t)((((lane >> 4) & 1) * 8 + (lane & 7)) * 144
                                    + ((lane >> 3) & 1) * 16);

    for (int it = 0; it < ITERS; it++) {
        const int s = it % 3;
        if (it >= ITERS - 2) { CPW0(); } else { CPW1(); }
        __syncthreads();
        const uint32_t kbase = sb + KOFF + (uint32_t)s * KST + lkv;
        const uint32_t vbase = sb + VOFF + (uint32_t)s * KST + lkv;

        float acc[2][8][4];
#pragma unroll
        for (int im = 0; im < 2; im++)
#pragma unroll
            for (int j = 0; j < 8; j++)
#pragma unroll
                for (int e = 0; e < 4; e++) acc[im][j][e] = 0.0f;
#pragma unroll
        for (int kc = 0; kc < 4; kc++) {             // 4 x k16 over head dim
            uint32_t kf[4][4];
#pragma unroll
            for (int tg = 0; tg < 4; tg++) LDSM4(kf[tg], kbase + kc * 32 + tg * (16 * 144));
#pragma unroll
            for (int im = 0; im < 2; im++)
#pragma unroll
                for (int j = 0; j < 8; j++)
                    mma_h(acc[im][j], Qf[im][kc], &kf[j >> 1][(j & 1) * 2]);
        }

        uint32_t w[2][2], w8[2][2];
#pragma unroll
        for (int im = 0; im < 2; im++) {
            w[im][0]  = mpr[im][it * 2];       w[im][1]  = mpr[im][it * 2 + 1];
            w8[im][0] = mpr[im][512 + it * 2]; w8[im][1] = mpr[im][512 + it * 2 + 1];
        }
#pragma unroll
        for (int st = 0; st < 4; st++) {
            uint32_t af[2][4];
#pragma unroll
            for (int im = 0; im < 2; im++)
#pragma unroll
                for (int jj = 0; jj < 2; jj++) {
                    const int j = st * 2 + jj;
                    const int bp = (j * 8) & 31;
                    const int wsel = (j >> 2);
                    const uint32_t wl = w[im][wsel], wh = w8[im][wsel];
                    float e00 = ex2a(((wl >> (bp + bpl)) & 1u)     ? acc[im][j][0] * cf : -12000.0f);
                    float e01 = ex2a(((wl >> (bp + bpl + 1)) & 1u) ? acc[im][j][1] * cf : -12000.0f);
                    float e10 = ex2a(((wh >> (bp + bpl)) & 1u)     ? acc[im][j][2] * cf : -12000.0f);
                    float e11 = ex2a(((wh >> (bp + bpl + 1)) & 1u) ? acc[im][j][3] * cf : -12000.0f);
                    rs[im][0] += e00 + e01;
                    rs[im][1] += e10 + e11;
                    af[im][jj * 2 + 0] = cvth2(e00, e01);
                    af[im][jj * 2 + 1] = cvth2(e10, e11);
                }
            uint32_t vf[4][4];
#pragma unroll
            for (int eg = 0; eg < 4; eg++) LDSM4(vf[eg], vbase + st * 32 + eg * (16 * 144));
#pragma unroll
            for (int im = 0; im < 2; im++)
#pragma unroll
                for (int eg = 0; eg < 4; eg++) {
                    mma_h(acc2[im][eg * 2 + 0], af[im], &vf[eg][0]);
                    mma_h(acc2[im][eg * 2 + 1], af[im], &vf[eg][2]);
                }
        }
        if (it + 2 < ITERS) {
            int sp = (it + 2) % 3;
            stage_k(sp, (it + 2) * TT);
            stage_v(sp, (it + 2) * TT);
            CPC();
        }
    }

    // row sums: quad shuffle (lanes in a quad share the same row)
#pragma unroll
    for (int im = 0; im < 2; im++)
#pragma unroll
        for (int r = 0; r < 2; r++) {
            rs[im][r] += __shfl_xor_sync(0xffffffffu, rs[im][r], 1);
            rs[im][r] += __shfl_xor_sync(0xffffffffu, rs[im][r], 2);
        }

    // epilogue: each warp owns its rows fully -> direct write, no smem
#pragma unroll
    for (int im = 0; im < 2; im++) {
        int row = s0 + wm * 32 + im * 16 + (lane >> 2);
        float inv0 = 1.0f / rs[im][0];
        float inv1 = 1.0f / rs[im][1];
#pragma unroll
        for (int je = 0; je < 8; je++) {
            int cl = je * 8 + (lane & 3) * 2;
            ((uint32_t*)O)[(((size_t)bh * S_ + row) * HD + cl) >> 1] =
                cvth2(acc2[im][je][0] * inv0, acc2[im][je][1] * inv0);
            ((uint32_t*)O)[(((size_t)bh * S_ + row + 8) * HD + cl) >> 1] =
                cvth2(acc2[im][je][2] * inv1, acc2[im][je][3] * inv1);
        }
    }
}

// ---------------- fused prep: conv_x + maskpack + transpose in ONE launch ----------------
// blocks [0, 8192): conv_x (512 f32 each)
// blocks [8192, 10240): maskpack (2048 blocks x 256 words)
// blocks [10240, 14336): transpose (4096 = 4 weights x 32 x 32 tiles)
__global__ __launch_bounds__(256)
void prep_all(const float* __restrict__ X, uint16_t* __restrict__ Xh,
              const int* __restrict__ mask, uint32_t* __restrict__ mp,
              const float* __restrict__ Wa, const float* __restrict__ Wb,
              const float* __restrict__ Wc, const float* __restrict__ Wd,
              uint16_t* __restrict__ Wt) {
    const int blk = blockIdx.x;
    if (blk < 8192) {                      // conv_x: x fp32 -> fp16 (8192*256*2 = 4.19M f32 pairs)
        size_t i = (size_t)blk * 256 + threadIdx.x;
        float2 v = ((const float2*)X)[i];
        ((uint32_t*)Xh)[i] = cvth2(v.x, v.y);
    } else if (blk < 10240) {              // maskpack
        int w = (blk - 8192) * 256 + threadIdx.x;
        const int4* src = (const int4*)mask + (size_t)w * 8;
        uint32_t bits = 0;
#pragma unroll
        for (int i = 0; i < 8; i++) {
            int4 v = src[i];
            bits |= (uint32_t)(v.x == 1) << (i * 4 + 0);
            bits |= (uint32_t)(v.y == 1) << (i * 4 + 1);
            bits |= (uint32_t)(v.z == 1) << (i * 4 + 2);
            bits |= (uint32_t)(v.w == 1) << (i * 4 + 3);
        }
        mp[w] = bits;
    } else {                               // transpose_h
        __shared__ float t[32][33];
        int id = blk - 10240;
        int z = id >> 10;                  // 1024 tiles per weight
        int ty32 = (id >> 5) & 31, tx32 = id & 31;
        const float* W = (z == 0) ? Wa : (z == 1) ? Wb : (z == 2) ? Wc : Wd;
        uint16_t* Wo = Wt + (size_t)z * DM * DM;
        const int tx = threadIdx.x & 31, ty = threadIdx.x >> 5;
        const int bx = tx32 * 32, by = ty32 * 32;
#pragma unroll
        for (int j = 0; j < 32; j += 8) t[ty + j][tx] = W[(size_t)(by + ty + j) * DM + bx + tx];
        __syncthreads();
#pragma unroll
        for (int j = 0; j < 32; j += 8)
            Wo[(size_t)(bx + ty + j) * DM + by + tx] = f2h(t[tx][ty + j]);
    }
}

// ---------------- launch ----------------
extern "C" void kernel_launch(void* const* d_in, const int* in_sizes, int n_in,
                              void* d_out, int out_size) {
    (void)in_sizes; (void)n_in; (void)out_size;
    const float* x    = (const float*)d_in[0];
    const int*   mask = (const int*)d_in[1];
    const float* W0   = (const float*)d_in[2];
    const float* b0   = (const float*)d_in[3];
    const float* W1   = (const float*)d_in[4];
    const float* b1   = (const float*)d_in[5];
    const float* W2   = (const float*)d_in[6];
    const float* b2   = (const float*)d_in[7];
    const float* Wo   = (const float*)d_in[8];
    const float* bo   = (const float*)d_in[9];
    float* out = (float*)d_out;

    uint16_t *xh, *qh, *kh, *oh, *wt, *vt;
    uint32_t *mpd;
    cudaGetSymbolAddress((void**)&xh,  g_xh);
    cudaGetSymbolAddress((void**)&qh,  g_qh);
    cudaGetSymbolAddress((void**)&kh,  g_kh);
    cudaGetSymbolAddress((void**)&oh,  g_oh);
    cudaGetSymbolAddress((void**)&wt,  g_wt);
    cudaGetSymbolAddress((void**)&vt,  g_vt);
    cudaGetSymbolAddress((void**)&mpd, g_mp);
    const size_t WP = (size_t)DM * DM;

    cudaFuncSetAttribute(gemm_h<0>, cudaFuncAttributeMaxDynamicSharedMemorySize, DSMEM);
    cudaFuncSetAttribute(gemm_h<2>, cudaFuncAttributeMaxDynamicSharedMemorySize, DSMEM);
    cudaFuncSetAttribute(gemm_kv,   cudaFuncAttributeMaxDynamicSharedMemorySize, DSMEM);
    cudaFuncSetAttribute(flash_attn, cudaFuncAttributeMaxDynamicSharedMemorySize, FSMEM);

    prep_all<<<14336, 256>>>(x, xh, mask, mpd, W0, W1, W2, Wo, wt);

    gemm_h<2><<<dim3(8, 32), 128, DSMEM>>>(xh, wt + 0 * WP, b0, nullptr, qh);
    gemm_kv<<<dim3(16, 32), 128, DSMEM>>>(qh, wt + 1 * WP, b1, b2, kh, vt);
    flash_attn<<<dim3(16, 32), 128, FSMEM>>>(qh, kh, vt, mpd, oh);
    gemm_h<0><<<dim3(8, 32), 128, DSMEM>>>(oh, wt + 3 * WP, bo, out, nullptr);
}